// round 4
// baseline (speedup 1.0000x reference)
#include <cuda_runtime.h>
#include <cuda_bf16.h>
#include <cstdint>

// BiLSTM-CRF forward, all fp32 (Viterbi argmax stability forbids low precision).
// Uses packed fma.rn.f32x2 for 2x fp32 throughput on sm_103a.
//
// Shapes: V=50000 E=512 H=512 HD=1024 B=64 L=512 T=16, START=14 STOP=15

#define Lq 512
#define Bq 64
#define Eq 512
#define Hq 512
#define NEGV -10000.0f

typedef unsigned long long u64;

// ---------------- scratch (__device__ globals) ----------------------------
__device__ float g_G[(size_t)32768 * 4096];      // input-proj gates [l*64+b][dir*2048 + g*512 + h]
__device__ float g_Wt[(size_t)512 * 4096];       // Wih^T combined  [k][n]
__device__ float g_WhT[2][(size_t)512 * 2048];   // Whh^T per dir   [k][n2048]
__device__ float g_hT[2][2][(size_t)512 * 64];   // [parity][dir][k][b]
__device__ float g_c[2][(size_t)64 * 512];       // [dir][b][h]
__device__ float g_hrow[(size_t)32768 * 1024];   // [l*64+b][dir*512+h]
__device__ float g_feats[(size_t)64 * 512 * 16]; // [b][l][t]

// ---------------- f32x2 helpers -------------------------------------------
__device__ __forceinline__ void ffma2(u64 &d, u64 a, u64 b) {
    asm("fma.rn.f32x2 %0, %1, %2, %0;" : "+l"(d) : "l"(a), "l"(b));
}
__device__ __forceinline__ u64 pack2(float x) {
    u64 r; asm("mov.b64 %0, {%1, %1};" : "=l"(r) : "f"(x)); return r;
}
__device__ __forceinline__ float2 unpack2(u64 v) {
    float2 f; asm("mov.b64 {%0, %1}, %2;" : "=f"(f.x), "=f"(f.y) : "l"(v)); return f;
}
__device__ __forceinline__ float sigf(float x) { return 1.0f / (1.0f + expf(-x)); }

// ---------------- prep kernels --------------------------------------------
__global__ void prep_wt(const float* __restrict__ wf, const float* __restrict__ wb) {
    int idx = blockIdx.x * 256 + threadIdx.x;        // 512*4096 = 2097152
    int k = idx >> 12, n = idx & 4095;
    g_Wt[idx] = (n < 2048) ? wf[n * 512 + k] : wb[(n - 2048) * 512 + k];
}
__global__ void prep_whT(const float* __restrict__ whf, const float* __restrict__ whb) {
    int idx = blockIdx.x * 256 + threadIdx.x;        // 2*512*2048 = 2097152
    int dir = idx >> 20; int r = idx & ((1 << 20) - 1);
    int k = r >> 11, n = r & 2047;
    const float* w = dir ? whb : whf;
    g_WhT[dir][(size_t)k * 2048 + n] = w[n * 512 + k];
}
__global__ void prep_state(const float* __restrict__ h0, const float* __restrict__ c0) {
    int idx = blockIdx.x * 256 + threadIdx.x;        // 2*64*512 = 65536
    int dir = idx >> 15; int r = idx & 32767;
    int b = r >> 9, k = r & 511;
    g_hT[0][dir][(size_t)k * 64 + b] = h0[idx];
    g_c[dir][(size_t)b * 512 + k]    = c0[idx];
}

// ---------------- input projection GEMM ------------------------------------
// G[m][n] = embed[tok(m)] . Wt[:,n] + bias[n];  m = l*64+b, tok = sent[b*512+l]
// tile 128(m) x 128(n), K-chunk 16, 256 threads, 8x8 per thread (m-paired f32x2)
__global__ void __launch_bounds__(256) gemm1(const int* __restrict__ sent,
                                             const float* __restrict__ embed,
                                             const float* __restrict__ bf,
                                             const float* __restrict__ bb) {
    __shared__ float As[16][128];
    __shared__ float Bs[16][128];
    __shared__ int toks[128];
    int tid = threadIdx.x;
    int n0 = blockIdx.x * 128;     // 32 n-tiles (fastest -> A-row L2 reuse)
    int m0 = blockIdx.y * 128;     // 256 m-tiles
    if (tid < 128) { int m = m0 + tid; toks[tid] = sent[(m & 63) * 512 + (m >> 6)]; }
    int tx = tid & 15, ty = tid >> 4;
    int lm = tid & 127, lkq = tid >> 7;    // A loader
    int ln4 = tid & 31, lk = tid >> 5;     // B loader
    u64 acc[4][8];
#pragma unroll
    for (int i = 0; i < 4; i++)
#pragma unroll
        for (int j = 0; j < 8; j++) acc[i][j] = 0ull;

    for (int k0 = 0; k0 < 512; k0 += 16) {
        __syncthreads();
        const float* arow = embed + (size_t)toks[lm] * 512 + k0;
#pragma unroll
        for (int r = 0; r < 2; r++) {
            int kk = (lkq + 2 * r) * 4;
            float4 v = *(const float4*)(arow + kk);
            As[kk + 0][lm] = v.x; As[kk + 1][lm] = v.y;
            As[kk + 2][lm] = v.z; As[kk + 3][lm] = v.w;
        }
#pragma unroll
        for (int r = 0; r < 2; r++) {
            int kk = lk + 8 * r;
            *(float4*)&Bs[kk][ln4 * 4] =
                *(const float4*)(g_Wt + (size_t)(k0 + kk) * 4096 + n0 + ln4 * 4);
        }
        __syncthreads();
#pragma unroll
        for (int k = 0; k < 16; k++) {
            u64 av[4];
#pragma unroll
            for (int i = 0; i < 4; i++) av[i] = *(const u64*)&As[k][ty * 8 + 2 * i];
#pragma unroll
            for (int j = 0; j < 8; j++) {
                u64 bv = pack2(Bs[k][j * 16 + tx]);
#pragma unroll
                for (int i = 0; i < 4; i++) ffma2(acc[i][j], av[i], bv);
            }
        }
    }
#pragma unroll
    for (int j = 0; j < 8; j++) {
        int n = n0 + j * 16 + tx;
        float bias = (n < 2048) ? bf[n] : bb[n - 2048];
#pragma unroll
        for (int i = 0; i < 4; i++) {
            float2 v = unpack2(acc[i][j]);
            size_t row = (size_t)(m0 + ty * 8 + 2 * i);
            g_G[row * 4096 + n]       = v.x + bias;
            g_G[(row + 1) * 4096 + n] = v.y + bias;
        }
    }
}

// ---------------- LSTM recurrence step -------------------------------------
// per step: gates[dir][b][g*512+h] = G[l][b][...] + h_prev . WhT ; then pointwise
// grid 64 = dir(2) x btile(2 of 32) x htile(16 of 32); 256 threads
__global__ void __launch_bounds__(256) lstm_step(int t) {
    __shared__ float Hs[32][32];
    __shared__ float Ws[32][128];
    int tid = threadIdx.x;
    int hblk = blockIdx.x & 15;
    int bblk = (blockIdx.x >> 4) & 1;
    int dir  = blockIdx.x >> 5;
    int h0 = hblk * 32, b0 = bblk * 32;
    int p = t & 1;
    const float* hT = g_hT[p][dir];
    const float* Wd = g_WhT[dir];
    int bp_ = tid >> 4;   // 0..15 (b-pair)
    int hp  = tid & 15;   // 0..15 (h-col pair)
    int lc4 = tid & 7, lk = tid >> 3;  // loaders: k 0..31, 8x float4

    u64 acc[2][4];
#pragma unroll
    for (int bi = 0; bi < 2; bi++)
#pragma unroll
        for (int g = 0; g < 4; g++) acc[bi][g] = 0ull;

    for (int k0 = 0; k0 < 512; k0 += 32) {
        __syncthreads();
        *(float4*)&Hs[lk][lc4 * 4] =
            *(const float4*)(hT + (size_t)(k0 + lk) * 64 + b0 + lc4 * 4);
#pragma unroll
        for (int g = 0; g < 4; g++)
            *(float4*)&Ws[lk][g * 32 + lc4 * 4] =
                *(const float4*)(Wd + (size_t)(k0 + lk) * 2048 + g * 512 + h0 + lc4 * 4);
        __syncthreads();
#pragma unroll 8
        for (int k = 0; k < 32; k++) {
            u64 a0 = pack2(Hs[k][2 * bp_]);
            u64 a1 = pack2(Hs[k][2 * bp_ + 1]);
#pragma unroll
            for (int g = 0; g < 4; g++) {
                u64 wv = *(const u64*)&Ws[k][g * 32 + 2 * hp];
                ffma2(acc[0][g], a0, wv);
                ffma2(acc[1][g], a1, wv);
            }
        }
    }

    int l = dir ? (511 - t) : t;
    int po = p ^ 1;
#pragma unroll
    for (int bi = 0; bi < 2; bi++) {
        int b = b0 + 2 * bp_ + bi;
        float2 gv[4];
#pragma unroll
        for (int g = 0; g < 4; g++) gv[g] = unpack2(acc[bi][g]);
        size_t grow = (size_t)(l * 64 + b) * 4096 + (size_t)dir * 2048;
#pragma unroll
        for (int ci = 0; ci < 2; ci++) {
            int h = h0 + 2 * hp + ci;
            float iv = (ci ? gv[0].y : gv[0].x) + g_G[grow + h];
            float fv = (ci ? gv[1].y : gv[1].x) + g_G[grow + 512 + h];
            float gg = (ci ? gv[2].y : gv[2].x) + g_G[grow + 1024 + h];
            float ov = (ci ? gv[3].y : gv[3].x) + g_G[grow + 1536 + h];
            float cp = g_c[dir][(size_t)b * 512 + h];
            float cn = sigf(fv) * cp + sigf(iv) * tanhf(gg);
            float hn = sigf(ov) * tanhf(cn);
            g_c[dir][(size_t)b * 512 + h] = cn;
            g_hT[po][dir][(size_t)h * 64 + b] = hn;
            g_hrow[(size_t)(l * 64 + b) * 1024 + dir * 512 + h] = hn;
        }
    }
}

// ---------------- tag projection -------------------------------------------
__global__ void __launch_bounds__(256) feats_kernel(const float* __restrict__ Wtag,
                                                    const float* __restrict__ btag) {
    int idx = blockIdx.x * 256 + threadIdx.x;   // 64*512*16 = 524288
    int t = idx & 15;
    int l = (idx >> 4) & 511;
    int b = idx >> 13;
    const float4* hr = (const float4*)(g_hrow + (size_t)(l * 64 + b) * 1024);
    const float4* wr = (const float4*)(Wtag + (size_t)t * 1024);
    float a0 = 0.f, a1 = 0.f;
#pragma unroll 8
    for (int k = 0; k < 256; k += 2) {
        float4 x = hr[k],     w = wr[k];
        float4 y = hr[k + 1], v = wr[k + 1];
        a0 += x.x * w.x + x.y * w.y + x.z * w.z + x.w * w.w;
        a1 += y.x * v.x + y.y * v.y + y.z * v.z + y.w * v.w;
    }
    g_feats[((size_t)b * 512 + l) * 16 + t] = a0 + a1 + btag[t];
}

// ---------------- Viterbi ---------------------------------------------------
__global__ void __launch_bounds__(32) viterbi_kernel(const float* __restrict__ trans,
                                                     float* __restrict__ out) {
    int b = blockIdx.x;
    int lane = threadIdx.x;           // 32 lanes, 16 active as tags
    __shared__ unsigned char bp[512][16];
    __shared__ float smax[16];
    bool active = lane < 16;
    int row = active ? lane : 15;
    float tr[16];
#pragma unroll
    for (int j = 0; j < 16; j++) tr[j] = trans[row * 16 + j];
    float fv = (lane == 14) ? 0.0f : NEGV;   // START=14

    const float* fb = g_feats + (size_t)b * 512 * 16;
    for (int l = 0; l < 512; l++) {
        float best = -3.4e38f;
        int arg = 0;
#pragma unroll
        for (int j = 0; j < 16; j++) {
            float s = __shfl_sync(0xffffffffu, fv, j) + tr[j];
            if (s > best) { best = s; arg = j; }
        }
        float nf = best + fb[l * 16 + row];
        if (active) bp[l][lane] = (unsigned char)arg;
        fv = nf;
    }
    // termination: term = fv + transitions[STOP] (STOP=15 row)
    float term = fv + trans[15 * 16 + row];
    if (active) smax[lane] = term;
    __syncwarp();
    if (lane == 0) {
        float best = smax[0]; int tag = 0;
        for (int j = 1; j < 16; j++) if (smax[j] > best) { best = smax[j]; tag = j; }
        out[b] = best;
        for (int l = 511; l >= 0; l--) {
            out[64 + b * 512 + l] = (float)tag;
            tag = bp[l][tag];
        }
    }
}

// ---------------- launch ----------------------------------------------------
extern "C" void kernel_launch(void* const* d_in, const int* in_sizes, int n_in,
                              void* d_out, int out_size) {
    const int*   sent  = (const int*)d_in[0];
    const float* embed = (const float*)d_in[1];
    const float* Wih_f = (const float*)d_in[2];
    const float* Whh_f = (const float*)d_in[3];
    const float* b_f   = (const float*)d_in[4];
    const float* Wih_b = (const float*)d_in[5];
    const float* Whh_b = (const float*)d_in[6];
    const float* b_b   = (const float*)d_in[7];
    const float* h0    = (const float*)d_in[8];
    const float* c0    = (const float*)d_in[9];
    const float* W_tag = (const float*)d_in[10];
    const float* b_tag = (const float*)d_in[11];
    const float* trans = (const float*)d_in[12];
    float* out = (float*)d_out;

    prep_wt<<<8192, 256>>>(Wih_f, Wih_b);
    prep_whT<<<8192, 256>>>(Whh_f, Whh_b);
    prep_state<<<256, 256>>>(h0, c0);

    gemm1<<<dim3(32, 256), 256>>>(sent, embed, b_f, b_b);

    for (int t = 0; t < 512; t++) lstm_step<<<64, 256>>>(t);

    feats_kernel<<<2048, 256>>>(W_tag, b_tag);
    viterbi_kernel<<<64, 32>>>(trans, out);
}

// round 5
// speedup vs baseline: 1.6724x; 1.6724x over previous
#include <cuda_runtime.h>
#include <cuda_bf16.h>
#include <cstdint>

// BiLSTM-CRF forward, all fp32 (Viterbi argmax stability forbids low precision).
// f32x2 packed FMA everywhere; persistent-kernel recurrence with grid barrier.
//
// Shapes: V=50000 E=512 H=512 HD=1024 B=64 L=512 T=16, START=14 STOP=15

#define NEGV -10000.0f

typedef unsigned long long u64;

// ---------------- scratch (__device__ globals) ----------------------------
__device__ float g_G[(size_t)32768 * 4096];       // input-proj gates [l*64+b][dir*2048 + g*512 + h]
__device__ float g_Wt[(size_t)512 * 4096];        // Wih^T combined  [k][n]
__device__ float g_WhT[2][(size_t)512 * 2048];    // Whh^T per dir   [k][g*512+h]
__device__ float g_hdup[2][2][512][128];          // [parity][dir][k(=h idx)][b duplicated pairs]
__device__ float g_hrow[(size_t)32768 * 1024];    // [l*64+b][dir*512+h]
__device__ float g_feats[(size_t)64 * 512 * 16];  // [b][l][t]
__device__ unsigned g_bar[2];                     // per-dir step barrier

// ---------------- f32x2 helpers -------------------------------------------
__device__ __forceinline__ void ffma2(u64 &d, u64 a, u64 b) {
    asm("fma.rn.f32x2 %0, %1, %2, %0;" : "+l"(d) : "l"(a), "l"(b));
}
__device__ __forceinline__ u64 pack2(float x) {
    u64 r; asm("mov.b64 %0, {%1, %1};" : "=l"(r) : "f"(x)); return r;
}
__device__ __forceinline__ float2 unpack2(u64 v) {
    float2 f; asm("mov.b64 {%0, %1}, %2;" : "=f"(f.x), "=f"(f.y) : "l"(v)); return f;
}
__device__ __forceinline__ float sigf(float x) { return 1.0f / (1.0f + expf(-x)); }

__device__ __forceinline__ void cp16(unsigned dst_sm, const float* src) {
    asm volatile("cp.async.cg.shared.global [%0], [%1], 16;\n" :: "r"(dst_sm), "l"(src));
}
template <int N> __device__ __forceinline__ void cp_wait() {
    asm volatile("cp.async.wait_group %0;\n" :: "n"(N) : "memory");
}
__device__ __forceinline__ void cp_commit() {
    asm volatile("cp.async.commit_group;\n" ::: "memory");
}

// ---------------- prep kernels --------------------------------------------
__global__ void prep_wt(const float* __restrict__ wf, const float* __restrict__ wb) {
    int idx = blockIdx.x * 256 + threadIdx.x;        // 512*4096
    int k = idx >> 12, n = idx & 4095;
    g_Wt[idx] = (n < 2048) ? wf[n * 512 + k] : wb[(n - 2048) * 512 + k];
}
__global__ void prep_whT(const float* __restrict__ whf, const float* __restrict__ whb) {
    int idx = blockIdx.x * 256 + threadIdx.x;        // 2*512*2048
    int dir = idx >> 20; int r = idx & ((1 << 20) - 1);
    int k = r >> 11, n = r & 2047;
    const float* w = dir ? whb : whf;
    g_WhT[dir][(size_t)k * 2048 + n] = w[n * 512 + k];
}
__global__ void prep_hdup(const float* __restrict__ h0) {
    int idx = blockIdx.x * 256 + threadIdx.x;        // 2*512*64 = 65536
    int dir = idx >> 15; int r = idx & 32767;
    int k = r >> 6, b = r & 63;
    float v = h0[((size_t)dir * 64 + b) * 512 + k];
    float2* dst = (float2*)&g_hdup[0][dir][0][0];
    dst[k * 64 + b] = make_float2(v, v);
}
__global__ void reset_bar() { g_bar[0] = 0; g_bar[1] = 0; }

// ---------------- input projection GEMM (unchanged from R3) ----------------
__global__ void __launch_bounds__(256) gemm1(const int* __restrict__ sent,
                                             const float* __restrict__ embed,
                                             const float* __restrict__ bf,
                                             const float* __restrict__ bb) {
    __shared__ float As[16][128];
    __shared__ float Bs[16][128];
    __shared__ int toks[128];
    int tid = threadIdx.x;
    int n0 = blockIdx.x * 128;
    int m0 = blockIdx.y * 128;
    if (tid < 128) { int m = m0 + tid; toks[tid] = sent[(m & 63) * 512 + (m >> 6)]; }
    int tx = tid & 15, ty = tid >> 4;
    int lm = tid & 127, lkq = tid >> 7;
    int ln4 = tid & 31, lk = tid >> 5;
    u64 acc[4][8];
#pragma unroll
    for (int i = 0; i < 4; i++)
#pragma unroll
        for (int j = 0; j < 8; j++) acc[i][j] = 0ull;

    for (int k0 = 0; k0 < 512; k0 += 16) {
        __syncthreads();
        const float* arow = embed + (size_t)toks[lm] * 512 + k0;
#pragma unroll
        for (int r = 0; r < 2; r++) {
            int kk = (lkq + 2 * r) * 4;
            float4 v = *(const float4*)(arow + kk);
            As[kk + 0][lm] = v.x; As[kk + 1][lm] = v.y;
            As[kk + 2][lm] = v.z; As[kk + 3][lm] = v.w;
        }
#pragma unroll
        for (int r = 0; r < 2; r++) {
            int kk = lk + 8 * r;
            *(float4*)&Bs[kk][ln4 * 4] =
                *(const float4*)(g_Wt + (size_t)(k0 + kk) * 4096 + n0 + ln4 * 4);
        }
        __syncthreads();
#pragma unroll
        for (int k = 0; k < 16; k++) {
            u64 av[4];
#pragma unroll
            for (int i = 0; i < 4; i++) av[i] = *(const u64*)&As[k][ty * 8 + 2 * i];
#pragma unroll
            for (int j = 0; j < 8; j++) {
                u64 bv = pack2(Bs[k][j * 16 + tx]);
#pragma unroll
                for (int i = 0; i < 4; i++) ffma2(acc[i][j], av[i], bv);
            }
        }
    }
#pragma unroll
    for (int j = 0; j < 8; j++) {
        int n = n0 + j * 16 + tx;
        float bias = (n < 2048) ? bf[n] : bb[n - 2048];
#pragma unroll
        for (int i = 0; i < 4; i++) {
            float2 v = unpack2(acc[i][j]);
            size_t row = (size_t)(m0 + ty * 8 + 2 * i);
            g_G[row * 4096 + n]       = v.x + bias;
            g_G[(row + 1) * 4096 + n] = v.y + bias;
        }
    }
}

// ---------------- persistent LSTM recurrence --------------------------------
// 128 blocks = 2 dirs x 64 h-tiles (8 h-cols); 128 threads = 32 b-pairs x 4 h-pairs.
// Whh slice smem-resident (64KB); h staged via cp.async double buffer (2x32KB);
// c-state in registers; per-dir global barrier between steps.
__global__ void __launch_bounds__(128, 1) lstm_persist(const float* __restrict__ c0) {
    extern __shared__ float sm[];
    float* Ws = sm;                  // [512][32] : [k][g*8+hh]
    float* Hs = sm + 512 * 32;       // [2][64][128] duplicated h chunks

    const int tid = threadIdx.x;
    const int dir = blockIdx.x >> 6;
    const int h0  = (blockIdx.x & 63) * 8;
    const int bp  = tid >> 2;        // 0..31
    const int hp  = tid & 3;         // 0..3

    // load weight slice once
    const float* Wd = g_WhT[dir];
    for (int i = tid; i < 512 * 32; i += 128) {
        int k = i >> 5, c = i & 31;
        Ws[i] = Wd[(size_t)k * 2048 + (c >> 3) * 512 + h0 + (c & 7)];
    }
    // c-state in registers: cells (2 b) x (2 h)
    float creg[2][2];
#pragma unroll
    for (int bi = 0; bi < 2; bi++)
#pragma unroll
        for (int ci = 0; ci < 2; ci++)
            creg[bi][ci] = c0[((size_t)dir * 64 + 2 * bp + bi) * 512 + h0 + 2 * hp + ci];
    __syncthreads();

    unsigned smHs = (unsigned)__cvta_generic_to_shared(Hs);

    for (int t = 0; t < 512; t++) {
        const int p = t & 1;
        const float* hsrc = &g_hdup[p][dir][0][0];   // 512*128 floats

        // issue chunk 0 (64 k rows = 8192 floats)
        {
#pragma unroll
            for (int i = 0; i < 16; i++)
                cp16(smHs + (unsigned)((i * 128 + tid) * 16), hsrc + (i * 128 + tid) * 4);
            cp_commit();
        }

        u64 acc[2][4];
#pragma unroll
        for (int bi = 0; bi < 2; bi++)
#pragma unroll
            for (int g = 0; g < 4; g++) acc[bi][g] = 0ull;

        for (int c = 0; c < 8; c++) {
            if (c < 7) {
                const float* src = hsrc + (c + 1) * 8192;
                unsigned dst = smHs + (unsigned)(((c + 1) & 1) * 32768);
#pragma unroll
                for (int i = 0; i < 16; i++)
                    cp16(dst + (unsigned)((i * 128 + tid) * 16), src + (i * 128 + tid) * 4);
                cp_commit();
                cp_wait<1>();
            } else {
                cp_wait<0>();
            }
            __syncthreads();
            const float* hb = Hs + (c & 1) * 8192 + 4 * bp;
            const float* wr = Ws + c * 64 * 32 + 2 * hp;
#pragma unroll 8
            for (int kk = 0; kk < 64; kk++) {
                ulonglong2 hv = *(const ulonglong2*)(hb + kk * 128);
#pragma unroll
                for (int g = 0; g < 4; g++) {
                    u64 w = *(const u64*)(wr + kk * 32 + g * 8);
                    ffma2(acc[0][g], hv.x, w);
                    ffma2(acc[1][g], hv.y, w);
                }
            }
            __syncthreads();
        }

        // ---- LSTM pointwise epilogue ----
        int l = dir ? (511 - t) : t;
        float hcell[2][2];
#pragma unroll
        for (int bi = 0; bi < 2; bi++) {
            int b = 2 * bp + bi;
            size_t grow = ((size_t)l * 64 + b) * 4096 + (size_t)dir * 2048 + h0 + 2 * hp;
            float2 gi = *(const float2*)&g_G[grow];
            float2 gf = *(const float2*)&g_G[grow + 512];
            float2 gg = *(const float2*)&g_G[grow + 1024];
            float2 go = *(const float2*)&g_G[grow + 1536];
            float2 ai = unpack2(acc[bi][0]);
            float2 af = unpack2(acc[bi][1]);
            float2 ag = unpack2(acc[bi][2]);
            float2 ao = unpack2(acc[bi][3]);
#pragma unroll
            for (int ci = 0; ci < 2; ci++) {
                float iv = (ci ? ai.y : ai.x) + (ci ? gi.y : gi.x);
                float fv = (ci ? af.y : af.x) + (ci ? gf.y : gf.x);
                float gv = (ci ? ag.y : ag.x) + (ci ? gg.y : gg.x);
                float ov = (ci ? ao.y : ao.x) + (ci ? go.y : go.x);
                float cn = sigf(fv) * creg[bi][ci] + sigf(iv) * tanhf(gv);
                creg[bi][ci] = cn;
                hcell[bi][ci] = sigf(ov) * tanhf(cn);
            }
            *(float2*)&g_hrow[((size_t)l * 64 + b) * 1024 + dir * 512 + h0 + 2 * hp] =
                make_float2(hcell[bi][0], hcell[bi][1]);
        }
        float* hd = &g_hdup[p ^ 1][dir][0][0];
#pragma unroll
        for (int ci = 0; ci < 2; ci++) {
            int h = h0 + 2 * hp + ci;
            float4 v = make_float4(hcell[0][ci], hcell[0][ci], hcell[1][ci], hcell[1][ci]);
            *(float4*)&hd[(size_t)h * 128 + 4 * bp] = v;
        }

        // ---- per-dir grid barrier ----
        if (t != 511) {
            __syncthreads();
            if (tid == 0) {
                __threadfence();
                atomicAdd(&g_bar[dir], 1u);
                unsigned target = 64u * (unsigned)(t + 1);
                while (atomicAdd(&g_bar[dir], 0u) < target) { }
                __threadfence();   // acquire + L1 flush (CCTL.IVALL)
            }
            __syncthreads();
        }
    }
}

// ---------------- tag projection (unchanged) --------------------------------
__global__ void __launch_bounds__(256) feats_kernel(const float* __restrict__ Wtag,
                                                    const float* __restrict__ btag) {
    int idx = blockIdx.x * 256 + threadIdx.x;   // 64*512*16
    int t = idx & 15;
    int l = (idx >> 4) & 511;
    int b = idx >> 13;
    const float4* hr = (const float4*)(g_hrow + (size_t)(l * 64 + b) * 1024);
    const float4* wr = (const float4*)(Wtag + (size_t)t * 1024);
    float a0 = 0.f, a1 = 0.f;
#pragma unroll 8
    for (int k = 0; k < 256; k += 2) {
        float4 x = hr[k],     w = wr[k];
        float4 y = hr[k + 1], v = wr[k + 1];
        a0 += x.x * w.x + x.y * w.y + x.z * w.z + x.w * w.w;
        a1 += y.x * v.x + y.y * v.y + y.z * v.z + y.w * v.w;
    }
    g_feats[((size_t)b * 512 + l) * 16 + t] = a0 + a1 + btag[t];
}

// ---------------- Viterbi (unchanged) ----------------------------------------
__global__ void __launch_bounds__(32) viterbi_kernel(const float* __restrict__ trans,
                                                     float* __restrict__ out) {
    int b = blockIdx.x;
    int lane = threadIdx.x;
    __shared__ unsigned char bp[512][16];
    __shared__ float smax[16];
    bool active = lane < 16;
    int row = active ? lane : 15;
    float tr[16];
#pragma unroll
    for (int j = 0; j < 16; j++) tr[j] = trans[row * 16 + j];
    float fv = (lane == 14) ? 0.0f : NEGV;   // START=14

    const float* fb = g_feats + (size_t)b * 512 * 16;
    for (int l = 0; l < 512; l++) {
        float best = -3.4e38f;
        int arg = 0;
#pragma unroll
        for (int j = 0; j < 16; j++) {
            float s = __shfl_sync(0xffffffffu, fv, j) + tr[j];
            if (s > best) { best = s; arg = j; }
        }
        float nf = best + fb[l * 16 + row];
        if (active) bp[l][lane] = (unsigned char)arg;
        fv = nf;
    }
    float term = fv + trans[15 * 16 + row];  // STOP=15
    if (active) smax[lane] = term;
    __syncwarp();
    if (lane == 0) {
        float best = smax[0]; int tag = 0;
        for (int j = 1; j < 16; j++) if (smax[j] > best) { best = smax[j]; tag = j; }
        out[b] = best;
        for (int l = 511; l >= 0; l--) {
            out[64 + b * 512 + l] = (float)tag;
            tag = bp[l][tag];
        }
    }
}

// ---------------- launch -----------------------------------------------------
extern "C" void kernel_launch(void* const* d_in, const int* in_sizes, int n_in,
                              void* d_out, int out_size) {
    const int*   sent  = (const int*)d_in[0];
    const float* embed = (const float*)d_in[1];
    const float* Wih_f = (const float*)d_in[2];
    const float* Whh_f = (const float*)d_in[3];
    const float* b_f   = (const float*)d_in[4];
    const float* Wih_b = (const float*)d_in[5];
    const float* Whh_b = (const float*)d_in[6];
    const float* b_b   = (const float*)d_in[7];
    const float* h0    = (const float*)d_in[8];
    const float* c0    = (const float*)d_in[9];
    const float* W_tag = (const float*)d_in[10];
    const float* b_tag = (const float*)d_in[11];
    const float* trans = (const float*)d_in[12];
    float* out = (float*)d_out;

    cudaFuncSetAttribute(lstm_persist, cudaFuncAttributeMaxDynamicSharedMemorySize, 131072);

    prep_wt<<<8192, 256>>>(Wih_f, Wih_b);
    prep_whT<<<8192, 256>>>(Whh_f, Whh_b);
    prep_hdup<<<256, 256>>>(h0);
    reset_bar<<<1, 1>>>();

    gemm1<<<dim3(32, 256), 256>>>(sent, embed, b_f, b_b);

    lstm_persist<<<128, 128, 131072>>>(c0);

    feats_kernel<<<2048, 256>>>(W_tag, b_tag);
    viterbi_kernel<<<64, 32>>>(trans, out);
}

// round 6
// speedup vs baseline: 1.9433x; 1.1620x over previous
#include <cuda_runtime.h>
#include <cuda_bf16.h>
#include <cstdint>

// BiLSTM-CRF forward, all fp32 (Viterbi argmax stability forbids low precision).
// f32x2 packed FMA; persistent recurrence: 128 blocks x 256 thr (k-split halves),
// smem-resident Whh slice, cp.async h/G staging, red.release/ld.acquire barrier.
//
// Shapes: V=50000 E=512 H=512 HD=1024 B=64 L=512 T=16, START=14 STOP=15

#define NEGV -10000.0f

typedef unsigned long long u64;

// smem float offsets for lstm_persist
#define SMW 0        // Ws  [0,16384)       512 x 32, gate-interleaved
#define SMH 16384    // Hs  [16384,32768)   2 halves x 2 bufs x 4096
#define SMG 32768    // Gs  [32768,34816)   gate slice for this step
#define SMR 34816    // Red [34816,36864)   cross-half partial sums
#define SMEM_BYTES (36864 * 4)

// ---------------- scratch (__device__ globals) ----------------------------
__device__ float g_G[(size_t)32768 * 4096];       // input-proj gates [l*64+b][dir*2048+g*512+h]
__device__ float g_Wt[(size_t)512 * 4096];        // Wih^T combined  [k][n]
__device__ float g_WhT[2][(size_t)512 * 2048];    // Whh^T per dir   [k][g*512+h]
__device__ float g_h[2][2][512][64];              // [parity][dir][h][b]
__device__ float g_hrow[(size_t)32768 * 1024];    // [l*64+b][dir*512+h]
__device__ float g_feats[(size_t)64 * 512 * 16];  // [b][l][t]
__device__ unsigned g_bar[2];                     // per-dir step barrier

// ---------------- helpers ---------------------------------------------------
__device__ __forceinline__ void ffma2(u64 &d, u64 a, u64 b) {
    asm("fma.rn.f32x2 %0, %1, %2, %0;" : "+l"(d) : "l"(a), "l"(b));
}
__device__ __forceinline__ u64 pack2(float x) {
    u64 r; asm("mov.b64 %0, {%1, %1};" : "=l"(r) : "f"(x)); return r;
}
__device__ __forceinline__ float2 unpack2(u64 v) {
    float2 f; asm("mov.b64 {%0, %1}, %2;" : "=f"(f.x), "=f"(f.y) : "l"(v)); return f;
}
__device__ __forceinline__ float sigf(float x) { return 1.0f / (1.0f + expf(-x)); }

__device__ __forceinline__ void cp16(unsigned dst_sm, const float* src) {
    asm volatile("cp.async.cg.shared.global [%0], [%1], 16;\n" :: "r"(dst_sm), "l"(src));
}
template <int N> __device__ __forceinline__ void cp_wait() {
    asm volatile("cp.async.wait_group %0;\n" :: "n"(N) : "memory");
}
__device__ __forceinline__ void cp_commit() {
    asm volatile("cp.async.commit_group;\n" ::: "memory");
}
__device__ __forceinline__ void bar_arrive(unsigned* p) {
    asm volatile("red.release.gpu.global.add.u32 [%0], %1;" :: "l"(p), "r"(1u) : "memory");
}
__device__ __forceinline__ unsigned ld_acq(const unsigned* p) {
    unsigned v; asm volatile("ld.acquire.gpu.global.u32 %0, [%1];" : "=r"(v) : "l"(p) : "memory");
    return v;
}
#define BAR_HALF(id) asm volatile("bar.sync %0, 128;" :: "r"(id) : "memory")

// ---------------- prep kernels ---------------------------------------------
// prepA: Wih^T re-layout + h0 transpose + barrier reset (one kernel)
__global__ void prepA(const float* __restrict__ wf, const float* __restrict__ wb,
                      const float* __restrict__ h0) {
    int idx = blockIdx.x * 256 + threadIdx.x;
    if (idx < 2) g_bar[idx] = 0;
    if (idx < 2097152) {                       // 512*4096
        int k = idx >> 12, n = idx & 4095;
        g_Wt[idx] = (n < 2048) ? wf[n * 512 + k] : wb[(n - 2048) * 512 + k];
    } else {
        int r2 = idx - 2097152;                // 2*512*64 = 65536
        if (r2 < 65536) {
            int dir = r2 >> 15; int r = r2 & 32767;
            int k = r >> 6, b = r & 63;
            g_h[0][dir][k][b] = h0[((size_t)dir * 64 + b) * 512 + k];
        }
    }
}
// prepB: Whh^T per dir
__global__ void prepB(const float* __restrict__ whf, const float* __restrict__ whb) {
    int idx = blockIdx.x * 256 + threadIdx.x;  // 2*512*2048
    int dir = idx >> 20; int r = idx & ((1 << 20) - 1);
    int k = r >> 11, n = r & 2047;
    const float* w = dir ? whb : whf;
    g_WhT[dir][(size_t)k * 2048 + n] = w[n * 512 + k];
}

// ---------------- input projection GEMM -------------------------------------
__global__ void __launch_bounds__(256) gemm1(const int* __restrict__ sent,
                                             const float* __restrict__ embed,
                                             const float* __restrict__ bf,
                                             const float* __restrict__ bb) {
    __shared__ float As[16][128];
    __shared__ float Bs[16][128];
    __shared__ int toks[128];
    int tid = threadIdx.x;
    int n0 = blockIdx.x * 128;
    int m0 = blockIdx.y * 128;
    if (tid < 128) { int m = m0 + tid; toks[tid] = sent[(m & 63) * 512 + (m >> 6)]; }
    int tx = tid & 15, ty = tid >> 4;
    int lm = tid & 127, lkq = tid >> 7;
    int ln4 = tid & 31, lk = tid >> 5;
    u64 acc[4][8];
#pragma unroll
    for (int i = 0; i < 4; i++)
#pragma unroll
        for (int j = 0; j < 8; j++) acc[i][j] = 0ull;

    for (int k0 = 0; k0 < 512; k0 += 16) {
        __syncthreads();
        const float* arow = embed + (size_t)toks[lm] * 512 + k0;
#pragma unroll
        for (int r = 0; r < 2; r++) {
            int kk = (lkq + 2 * r) * 4;
            float4 v = *(const float4*)(arow + kk);
            As[kk + 0][lm] = v.x; As[kk + 1][lm] = v.y;
            As[kk + 2][lm] = v.z; As[kk + 3][lm] = v.w;
        }
#pragma unroll
        for (int r = 0; r < 2; r++) {
            int kk = lk + 8 * r;
            *(float4*)&Bs[kk][ln4 * 4] =
                *(const float4*)(g_Wt + (size_t)(k0 + kk) * 4096 + n0 + ln4 * 4);
        }
        __syncthreads();
#pragma unroll
        for (int k = 0; k < 16; k++) {
            u64 av[4];
#pragma unroll
            for (int i = 0; i < 4; i++) av[i] = *(const u64*)&As[k][ty * 8 + 2 * i];
#pragma unroll
            for (int j = 0; j < 8; j++) {
                u64 bv = pack2(Bs[k][j * 16 + tx]);
#pragma unroll
                for (int i = 0; i < 4; i++) ffma2(acc[i][j], av[i], bv);
            }
        }
    }
#pragma unroll
    for (int j = 0; j < 8; j++) {
        int n = n0 + j * 16 + tx;
        float bias = (n < 2048) ? bf[n] : bb[n - 2048];
#pragma unroll
        for (int i = 0; i < 4; i++) {
            float2 v = unpack2(acc[i][j]);
            size_t row = (size_t)(m0 + ty * 8 + 2 * i);
            g_G[row * 4096 + n]       = v.x + bias;
            g_G[(row + 1) * 4096 + n] = v.y + bias;
        }
    }
}

// ---------------- persistent LSTM recurrence --------------------------------
// 128 blocks = 2 dirs x 64 h-tiles (8 h-cols). 256 threads = 2 k-halves x
// (32 b-pairs x 4 h-pairs). Whh slice smem-resident; h + G staged by cp.async;
// c-state in registers; red.release/ld.acquire grid barrier per step.
__global__ void __launch_bounds__(256, 1) lstm_persist(const float* __restrict__ c0) {
    extern __shared__ float smf[];
    const int tid  = threadIdx.x;
    const int kh   = tid >> 7;        // k half: 0 -> k[0,256), 1 -> k[256,512)
    const int wtid = tid & 127;
    const int bp   = wtid >> 2;       // 0..31
    const int hp   = wtid & 3;        // 0..3
    const int dir  = blockIdx.x >> 6;
    const int h0   = (blockIdx.x & 63) * 8;
    const int b    = 2 * bp + kh;     // this thread's epilogue batch index

    unsigned smb = (unsigned)__cvta_generic_to_shared(smf);

    // Whh slice, gate-interleaved: Ws[k*32 + hp*8 + g*2 + ci]
    const float* Wd = g_WhT[dir];
    for (int i = tid; i < 16384; i += 256) {
        int k = i >> 5, c = i & 31;
        smf[SMW + i] = Wd[(size_t)k * 2048 + ((c >> 1) & 3) * 512 + h0 + 2 * (c >> 3) + (c & 1)];
    }
    float creg[2];
    creg[0] = c0[((size_t)dir * 64 + b) * 512 + h0 + 2 * hp];
    creg[1] = c0[((size_t)dir * 64 + b) * 512 + h0 + 2 * hp + 1];
    __syncthreads();

    for (int t = 0; t < 512; t++) {
        const int p = t & 1;
        const int l = dir ? (511 - t) : t;
        const float* hsrc = &g_h[p][dir][0][0];   // 512*64 floats

        // group 0: G gate-slice prefetch + chunk 0 of this half
        {
            int gb = tid & 63, gg = tid >> 6;
            const float* gsrc = g_G + ((size_t)l * 64 + gb) * 4096
                              + (size_t)dir * 2048 + (size_t)gg * 512 + h0;
            unsigned gd = smb + (unsigned)((SMG + (gg * 64 + gb) * 8) * 4);
            cp16(gd, gsrc); cp16(gd + 16, gsrc + 4);

            const float* s = hsrc + (kh * 4) * 4096;
            unsigned d0 = smb + (unsigned)((SMH + (kh * 2) * 4096) * 4);
#pragma unroll
            for (int i = 0; i < 8; i++) { int f = i * 128 + wtid; cp16(d0 + f * 16, s + f * 4); }
            cp_commit();
        }

        u64 acc[2][4];
#pragma unroll
        for (int bi = 0; bi < 2; bi++)
#pragma unroll
            for (int g = 0; g < 4; g++) acc[bi][g] = 0ull;

#pragma unroll
        for (int c = 0; c < 4; c++) {
            if (c < 3) {
                const float* s = hsrc + (kh * 4 + c + 1) * 4096;
                unsigned dd = smb + (unsigned)((SMH + (kh * 2 + ((c + 1) & 1)) * 4096) * 4);
#pragma unroll
                for (int i = 0; i < 8; i++) { int f = i * 128 + wtid; cp16(dd + f * 16, s + f * 4); }
                cp_commit();
                cp_wait<1>();
            } else {
                cp_wait<0>();
            }
            BAR_HALF(1 + kh);
            const float* Hb = smf + SMH + (kh * 2 + (c & 1)) * 4096 + 2 * bp;
            const float* Wr = smf + SMW + (kh * 256 + c * 64) * 32 + hp * 8;
#pragma unroll 8
            for (int kk = 0; kk < 64; kk++) {
                float2 h2 = *(const float2*)(Hb + kk * 64);
                u64 a0 = pack2(h2.x), a1 = pack2(h2.y);
                ulonglong2 wA = *(const ulonglong2*)(Wr + kk * 32);
                ulonglong2 wB = *(const ulonglong2*)(Wr + kk * 32 + 4);
                ffma2(acc[0][0], a0, wA.x); ffma2(acc[1][0], a1, wA.x);
                ffma2(acc[0][1], a0, wA.y); ffma2(acc[1][1], a1, wA.y);
                ffma2(acc[0][2], a0, wB.x); ffma2(acc[1][2], a1, wB.x);
                ffma2(acc[0][3], a0, wB.y); ffma2(acc[1][3], a1, wB.y);
            }
            BAR_HALF(1 + kh);
        }

        // exchange partials: each half keeps bi==kh, ships bi==1-kh
        __syncthreads();
        {
            u64* red = (u64*)(smf + SMR) + (kh * 128 + wtid) * 4;
#pragma unroll
            for (int g = 0; g < 4; g++) red[g] = acc[1 - kh][g];
        }
        __syncthreads();

        // epilogue: 2 cells per thread
        {
            const u64* red = (const u64*)(smf + SMR) + ((1 - kh) * 128 + wtid) * 4;
            float2 s[4];
#pragma unroll
            for (int g = 0; g < 4; g++) {
                float2 m = unpack2(acc[kh][g]);
                float2 o = unpack2(red[g]);
                s[g] = make_float2(m.x + o.x, m.y + o.y);
            }
            const float* Gp = smf + SMG + b * 8 + 2 * hp;   // + g*512
            float hcell[2];
#pragma unroll
            for (int ci = 0; ci < 2; ci++) {
                float iv = (ci ? s[0].y : s[0].x) + Gp[0 * 512 + ci];
                float fv = (ci ? s[1].y : s[1].x) + Gp[1 * 512 + ci];
                float gv = (ci ? s[2].y : s[2].x) + Gp[2 * 512 + ci];
                float ov = (ci ? s[3].y : s[3].x) + Gp[3 * 512 + ci];
                float cn = sigf(fv) * creg[ci] + sigf(iv) * tanhf(gv);
                creg[ci] = cn;
                hcell[ci] = sigf(ov) * tanhf(cn);
            }
            *(float2*)&g_hrow[((size_t)l * 64 + b) * 1024 + dir * 512 + h0 + 2 * hp] =
                make_float2(hcell[0], hcell[1]);
            float* hn = &g_h[p ^ 1][dir][0][0];
            hn[(h0 + 2 * hp) * 64 + b]     = hcell[0];
            hn[(h0 + 2 * hp + 1) * 64 + b] = hcell[1];
        }

        // grid barrier (per dir)
        if (t != 511) {
            __syncthreads();
            if (tid == 0) {
                bar_arrive(&g_bar[dir]);
                unsigned target = 64u * (unsigned)(t + 1);
                while (ld_acq(&g_bar[dir]) < target) { }
            }
            __syncthreads();
        }
    }
}

// ---------------- tag projection ---------------------------------------------
__global__ void __launch_bounds__(256) feats_kernel(const float* __restrict__ Wtag,
                                                    const float* __restrict__ btag) {
    int idx = blockIdx.x * 256 + threadIdx.x;   // 64*512*16
    int t = idx & 15;
    int l = (idx >> 4) & 511;
    int b = idx >> 13;
    const float4* hr = (const float4*)(g_hrow + (size_t)(l * 64 + b) * 1024);
    const float4* wr = (const float4*)(Wtag + (size_t)t * 1024);
    float a0 = 0.f, a1 = 0.f;
#pragma unroll 8
    for (int k = 0; k < 256; k += 2) {
        float4 x = hr[k],     w = wr[k];
        float4 y = hr[k + 1], v = wr[k + 1];
        a0 += x.x * w.x + x.y * w.y + x.z * w.z + x.w * w.w;
        a1 += y.x * v.x + y.y * v.y + y.z * v.z + y.w * v.w;
    }
    g_feats[((size_t)b * 512 + l) * 16 + t] = a0 + a1 + btag[t];
}

// ---------------- Viterbi -----------------------------------------------------
__global__ void __launch_bounds__(32) viterbi_kernel(const float* __restrict__ trans,
                                                     float* __restrict__ out) {
    int b = blockIdx.x;
    int lane = threadIdx.x;
    __shared__ unsigned char bp[512][16];
    __shared__ float smax[16];
    bool active = lane < 16;
    int row = active ? lane : 15;
    float tr[16];
#pragma unroll
    for (int j = 0; j < 16; j++) tr[j] = trans[row * 16 + j];
    float fv = (lane == 14) ? 0.0f : NEGV;   // START=14

    const float* fb = g_feats + (size_t)b * 512 * 16;
    for (int l = 0; l < 512; l++) {
        float best = -3.4e38f;
        int arg = 0;
#pragma unroll
        for (int j = 0; j < 16; j++) {
            float s = __shfl_sync(0xffffffffu, fv, j) + tr[j];
            if (s > best) { best = s; arg = j; }
        }
        float nf = best + fb[l * 16 + row];
        if (active) bp[l][lane] = (unsigned char)arg;
        fv = nf;
    }
    float term = fv + trans[15 * 16 + row];  // STOP=15
    if (active) smax[lane] = term;
    __syncwarp();
    if (lane == 0) {
        float best = smax[0]; int tag = 0;
        for (int j = 1; j < 16; j++) if (smax[j] > best) { best = smax[j]; tag = j; }
        out[b] = best;
        for (int l = 511; l >= 0; l--) {
            out[64 + b * 512 + l] = (float)tag;
            tag = bp[l][tag];
        }
    }
}

// ---------------- launch -------------------------------------------------------
extern "C" void kernel_launch(void* const* d_in, const int* in_sizes, int n_in,
                              void* d_out, int out_size) {
    const int*   sent  = (const int*)d_in[0];
    const float* embed = (const float*)d_in[1];
    const float* Wih_f = (const float*)d_in[2];
    const float* Whh_f = (const float*)d_in[3];
    const float* b_f   = (const float*)d_in[4];
    const float* Wih_b = (const float*)d_in[5];
    const float* Whh_b = (const float*)d_in[6];
    const float* b_b   = (const float*)d_in[7];
    const float* h0    = (const float*)d_in[8];
    const float* c0    = (const float*)d_in[9];
    const float* W_tag = (const float*)d_in[10];
    const float* b_tag = (const float*)d_in[11];
    const float* trans = (const float*)d_in[12];
    float* out = (float*)d_out;

    cudaFuncSetAttribute(lstm_persist, cudaFuncAttributeMaxDynamicSharedMemorySize, SMEM_BYTES);

    prepA<<<8448, 256>>>(Wih_f, Wih_b, h0);              // launch 1
    prepB<<<8192, 256>>>(Whh_f, Whh_b);                  // launch 2
    gemm1<<<dim3(32, 256), 256>>>(sent, embed, b_f, b_b); // launch 3
    lstm_persist<<<128, 256, SMEM_BYTES>>>(c0);          // launch 4 (ncu slot)
    feats_kernel<<<2048, 256>>>(W_tag, b_tag);           // launch 5
    viterbi_kernel<<<64, 32>>>(trans, out);              // launch 6
}

// round 7
// speedup vs baseline: 2.0053x; 1.0319x over previous
#include <cuda_runtime.h>
#include <cuda_bf16.h>
#include <cstdint>

// BiLSTM-CRF forward, all fp32 (Viterbi argmax stability forbids low precision).
// f32x2 packed FMA; persistent recurrence: 128 blocks x 512 thr (k-split 4-way),
// smem-resident Whh slice, cp.async staging, barrier-overlapped G prefetch.
//
// Shapes: V=50000 E=512 H=512 HD=1024 B=64 L=512 T=16, START=14 STOP=15

#define NEGV -10000.0f

typedef unsigned long long u64;

// smem float offsets for lstm_persist
#define SMW 0        // Ws  [0,16384)        512 x 32 gate-interleaved weights
#define SMH 16384    // Hs  [16384,32768)    4 quarters x 2 bufs x 2048
#define SMG 32768    // Gs  [32768,36864)    2 bufs x 2048 gate slice
#define SMR 36864    // Red [36864,45056)    4096 u64 partial sums
#define SM_FLOATS 45056
#define SMEM_BYTES (SM_FLOATS * 4)

// ---------------- scratch (__device__ globals) ----------------------------
__device__ float g_G[(size_t)32768 * 4096];       // input-proj gates [l*64+b][dir*2048+g*512+h]
__device__ float g_Wt[(size_t)512 * 4096];        // Wih^T combined  [k][n]
__device__ float g_WhT[2][(size_t)512 * 2048];    // Whh^T per dir   [k][g*512+h]
__device__ float g_h[2][2][512][64];              // [parity][dir][h][b]
__device__ float g_hrow[(size_t)32768 * 1024];    // [l*64+b][dir*512+h]
__device__ float g_feats[(size_t)64 * 512 * 16];  // [b][l][t]
__device__ unsigned g_bar[2];                     // per-dir step barrier

// ---------------- helpers ---------------------------------------------------
__device__ __forceinline__ void ffma2(u64 &d, u64 a, u64 b) {
    asm("fma.rn.f32x2 %0, %1, %2, %0;" : "+l"(d) : "l"(a), "l"(b));
}
__device__ __forceinline__ u64 pack2(float x) {
    u64 r; asm("mov.b64 %0, {%1, %1};" : "=l"(r) : "f"(x)); return r;
}
__device__ __forceinline__ float2 unpack2(u64 v) {
    float2 f; asm("mov.b64 {%0, %1}, %2;" : "=f"(f.x), "=f"(f.y) : "l"(v)); return f;
}
__device__ __forceinline__ float sigf(float x) { return 1.0f / (1.0f + expf(-x)); }

__device__ __forceinline__ void cp16(unsigned dst_sm, const float* src) {
    asm volatile("cp.async.cg.shared.global [%0], [%1], 16;\n" :: "r"(dst_sm), "l"(src));
}
template <int N> __device__ __forceinline__ void cp_wait() {
    asm volatile("cp.async.wait_group %0;\n" :: "n"(N) : "memory");
}
__device__ __forceinline__ void cp_commit() {
    asm volatile("cp.async.commit_group;\n" ::: "memory");
}
__device__ __forceinline__ void bar_arrive(unsigned* p) {
    asm volatile("red.release.gpu.global.add.u32 [%0], %1;" :: "l"(p), "r"(1u) : "memory");
}
__device__ __forceinline__ unsigned ld_acq(const unsigned* p) {
    unsigned v; asm volatile("ld.acquire.gpu.global.u32 %0, [%1];" : "=r"(v) : "l"(p) : "memory");
    return v;
}
#define BARQ(id) asm volatile("bar.sync %0, 128;" :: "r"(id) : "memory")

// ---------------- prep kernels ---------------------------------------------
__global__ void prepA(const float* __restrict__ wf, const float* __restrict__ wb,
                      const float* __restrict__ h0) {
    int idx = blockIdx.x * 256 + threadIdx.x;
    if (idx < 2) g_bar[idx] = 0;
    if (idx < 2097152) {                       // 512*4096
        int k = idx >> 12, n = idx & 4095;
        g_Wt[idx] = (n < 2048) ? wf[n * 512 + k] : wb[(n - 2048) * 512 + k];
    } else {
        int r2 = idx - 2097152;                // 2*512*64
        if (r2 < 65536) {
            int dir = r2 >> 15; int r = r2 & 32767;
            int k = r >> 6, b = r & 63;
            g_h[0][dir][k][b] = h0[((size_t)dir * 64 + b) * 512 + k];
        }
    }
}
__global__ void prepB(const float* __restrict__ whf, const float* __restrict__ whb) {
    int idx = blockIdx.x * 256 + threadIdx.x;  // 2*512*2048
    int dir = idx >> 20; int r = idx & ((1 << 20) - 1);
    int k = r >> 11, n = r & 2047;
    const float* w = dir ? whb : whf;
    g_WhT[dir][(size_t)k * 2048 + n] = w[n * 512 + k];
}

// ---------------- input projection GEMM (cp.async 2-stage) ------------------
// G[m][n] = embed[tok(m)] . Wt[:,n] + bias[n];  m = l*64+b
// tile 128x128, K-chunk 16; acc = f32x2 over n-pairs (A [m][k], B [k][n]).
__global__ void __launch_bounds__(256) gemm1(const int* __restrict__ sent,
                                             const float* __restrict__ embed,
                                             const float* __restrict__ bf,
                                             const float* __restrict__ bb) {
    __shared__ float As[2][128][16];
    __shared__ float Bs[2][16][128];
    __shared__ int toks[128];
    int tid = threadIdx.x;
    int n0 = blockIdx.x * 128;
    int m0 = blockIdx.y * 128;
    if (tid < 128) { int m = m0 + tid; toks[tid] = sent[(m & 63) * 512 + (m >> 6)]; }
    __syncthreads();
    int tx = tid & 15, ty = tid >> 4;
    unsigned smA = (unsigned)__cvta_generic_to_shared(&As[0][0][0]);
    unsigned smB = (unsigned)__cvta_generic_to_shared(&Bs[0][0][0]);

    u64 acc[8][4];
#pragma unroll
    for (int i = 0; i < 8; i++)
#pragma unroll
        for (int j = 0; j < 4; j++) acc[i][j] = 0ull;

    // stage issue: 2 cp16 for A + 2 cp16 for B per thread
    auto issue = [&](int k0, int buf) {
#pragma unroll
        for (int r = 0; r < 2; r++) {
            int idx = tid * 2 + r;
            int am = idx >> 2, aq = idx & 3;
            cp16(smA + (unsigned)(((buf * 128 + am) * 16 + aq * 4) * 4),
                 embed + (size_t)toks[am] * 512 + k0 + aq * 4);
            int bk = idx >> 5, bn = idx & 31;
            cp16(smB + (unsigned)(((buf * 16 + bk) * 128 + bn * 4) * 4),
                 g_Wt + (size_t)(k0 + bk) * 4096 + n0 + bn * 4);
        }
        cp_commit();
    };

    issue(0, 0);
    for (int c = 0; c < 32; c++) {
        cp_wait<0>();
        __syncthreads();
        if (c < 31) issue((c + 1) * 16, (c + 1) & 1);
        const int buf = c & 1;
#pragma unroll
        for (int k = 0; k < 16; k++) {
            u64 bv[4];
#pragma unroll
            for (int j = 0; j < 4; j++)
                bv[j] = *(const u64*)&Bs[buf][k][(j * 16 + tx) * 2];
#pragma unroll
            for (int i = 0; i < 8; i++) {
                u64 av = pack2(As[buf][ty * 8 + i][k]);
#pragma unroll
                for (int j = 0; j < 4; j++) ffma2(acc[i][j], av, bv[j]);
            }
        }
    }
#pragma unroll
    for (int j = 0; j < 4; j++) {
        int n = n0 + (j * 16 + tx) * 2;
        float2 bias;
        bias.x = (n < 2048) ? bf[n] : bb[n - 2048];
        bias.y = (n + 1 < 2048) ? bf[n + 1] : bb[n + 1 - 2048];
#pragma unroll
        for (int i = 0; i < 8; i++) {
            float2 v = unpack2(acc[i][j]);
            size_t row = (size_t)(m0 + ty * 8 + i);
            *(float2*)&g_G[row * 4096 + n] = make_float2(v.x + bias.x, v.y + bias.y);
        }
    }
}

// ---------------- persistent LSTM recurrence --------------------------------
// 128 blocks = 2 dirs x 64 h-tiles (8 h-cols). 512 threads = 4 k-quarters x
// (32 b-pairs x 4 h-pairs). Whh slice smem-resident; h + G staged by cp.async;
// owner threads (tid<256) reduce partials + run LSTM pointwise epilogue.
__global__ void __launch_bounds__(512, 1) lstm_persist(const float* __restrict__ c0) {
    extern __shared__ float smf[];
    const int tid  = threadIdx.x;
    const int q    = tid >> 7;        // k quarter
    const int wtid = tid & 127;
    const int bp   = wtid >> 2;       // 0..31
    const int hp   = wtid & 3;        // 0..3
    const int dir  = blockIdx.x >> 6;
    const int h0   = (blockIdx.x & 63) * 8;
    unsigned smb = (unsigned)__cvta_generic_to_shared(smf);

    // Whh slice, gate-interleaved: Ws[k*32 + hp*8 + g*2 + ci]
    const float* Wd = g_WhT[dir];
    for (int i = tid; i < 16384; i += 512) {
        int k = i >> 5, c = i & 31;
        smf[SMW + i] = Wd[(size_t)k * 2048 + ((c >> 1) & 3) * 512 + h0 + 2 * (c >> 3) + (c & 1)];
    }
    // owner cell (tid < 256): cell = (obp, ohp, obi)
    const int obp = tid >> 3, ohp = (tid >> 1) & 3, obi = tid & 1;
    const int ob  = 2 * obp + obi;
    float creg[2] = {0.f, 0.f};
    if (tid < 256) {
        creg[0] = c0[((size_t)dir * 64 + ob) * 512 + h0 + 2 * ohp];
        creg[1] = c0[((size_t)dir * 64 + ob) * 512 + h0 + 2 * ohp + 1];
    }
    // G prefetch mapping
    const int gg = tid >> 7, gb = (tid >> 1) & 63, gh = tid & 1;
    __syncthreads();

    // prefetch G(0) into SMG buf 0
    {
        int l0 = dir ? 511 : 0;
        const float* gsrc = g_G + ((size_t)l0 * 64 + gb) * 4096 + (size_t)dir * 2048
                          + (size_t)gg * 512 + h0 + gh * 4;
        cp16(smb + (unsigned)((SMG + (gg * 64 + gb) * 8 + gh * 4) * 4), gsrc);
        cp_commit();
    }

    for (int t = 0; t < 512; t++) {
        const int p = t & 1;
        const int l = dir ? (511 - t) : t;
        const float* hsrc = &g_h[p][dir][0][0];   // 512 x 64 floats

        // chunk 0 of this quarter (32 k rows x 64 b = 2048 floats)
        {
            const float* s = hsrc + (q * 128) * 64;
            unsigned dd = smb + (unsigned)((SMH + (q * 2) * 2048) * 4);
#pragma unroll
            for (int r = 0; r < 4; r++) { int f = r * 128 + wtid; cp16(dd + f * 16, s + f * 4); }
            cp_commit();
        }

        u64 acc[2][4];
#pragma unroll
        for (int bi = 0; bi < 2; bi++)
#pragma unroll
            for (int g = 0; g < 4; g++) acc[bi][g] = 0ull;

#pragma unroll
        for (int c = 0; c < 4; c++) {
            if (c < 3) {
                const float* s = hsrc + (q * 128 + (c + 1) * 32) * 64;
                unsigned dd = smb + (unsigned)((SMH + (q * 2 + ((c + 1) & 1)) * 2048) * 4);
#pragma unroll
                for (int r = 0; r < 4; r++) { int f = r * 128 + wtid; cp16(dd + f * 16, s + f * 4); }
                cp_commit();
                cp_wait<1>();
            } else {
                cp_wait<0>();
            }
            BARQ(1 + q);
            const float* Hb = smf + SMH + (q * 2 + (c & 1)) * 2048 + 2 * bp;
            const float* Wr = smf + SMW + (q * 128 + c * 32) * 32 + hp * 8;
#pragma unroll 8
            for (int kk = 0; kk < 32; kk++) {
                float2 h2 = *(const float2*)(Hb + kk * 64);
                u64 a0 = pack2(h2.x), a1 = pack2(h2.y);
                ulonglong2 wA = *(const ulonglong2*)(Wr + kk * 32);
                ulonglong2 wB = *(const ulonglong2*)(Wr + kk * 32 + 4);
                ffma2(acc[0][0], a0, wA.x); ffma2(acc[1][0], a1, wA.x);
                ffma2(acc[0][1], a0, wA.y); ffma2(acc[1][1], a1, wA.y);
                ffma2(acc[0][2], a0, wB.x); ffma2(acc[1][2], a1, wB.x);
                ffma2(acc[0][3], a0, wB.y); ffma2(acc[1][3], a1, wB.y);
            }
            BARQ(1 + q);
        }

        // exchange partials
        __syncthreads();
        {
            u64* red = (u64*)(smf + SMR) + tid * 8;
#pragma unroll
            for (int g = 0; g < 4; g++) { red[g] = acc[0][g]; red[4 + g] = acc[1][g]; }
        }
        __syncthreads();

        // owners: reduce 4 quarters, epilogue
        if (tid < 256) {
            const int wsrc = obp * 4 + ohp;
            float2 s[4] = {make_float2(0.f,0.f),make_float2(0.f,0.f),
                           make_float2(0.f,0.f),make_float2(0.f,0.f)};
            const u64* red = (const u64*)(smf + SMR);
#pragma unroll
            for (int qq = 0; qq < 4; qq++) {
                const u64* rp = red + ((size_t)(qq * 128 + wsrc)) * 8 + obi * 4;
#pragma unroll
                for (int g = 0; g < 4; g++) {
                    float2 v = unpack2(rp[g]);
                    s[g].x += v.x; s[g].y += v.y;
                }
            }
            const float* Gp = smf + SMG + p * 2048 + ob * 8 + 2 * ohp;  // + g*512
            float hcell[2];
#pragma unroll
            for (int ci = 0; ci < 2; ci++) {
                float iv = (ci ? s[0].y : s[0].x) + Gp[0 * 512 + ci];
                float fv = (ci ? s[1].y : s[1].x) + Gp[1 * 512 + ci];
                float gv = (ci ? s[2].y : s[2].x) + Gp[2 * 512 + ci];
                float ov = (ci ? s[3].y : s[3].x) + Gp[3 * 512 + ci];
                float cn = sigf(fv) * creg[ci] + sigf(iv) * tanhf(gv);
                creg[ci] = cn;
                hcell[ci] = sigf(ov) * tanhf(cn);
            }
            *(float2*)&g_hrow[((size_t)l * 64 + ob) * 1024 + dir * 512 + h0 + 2 * ohp] =
                make_float2(hcell[0], hcell[1]);
            float* hn = &g_h[p ^ 1][dir][0][0];
            hn[(h0 + 2 * ohp) * 64 + ob]     = hcell[0];
            hn[(h0 + 2 * ohp + 1) * 64 + ob] = hcell[1];
        }

        if (t != 511) {
            __syncthreads();
            // overlap: prefetch next step's G while waiting on the grid barrier
            {
                int ln = dir ? (510 - t) : (t + 1);
                const float* gsrc = g_G + ((size_t)ln * 64 + gb) * 4096 + (size_t)dir * 2048
                                  + (size_t)gg * 512 + h0 + gh * 4;
                cp16(smb + (unsigned)((SMG + ((t + 1) & 1) * 2048 + (gg * 64 + gb) * 8 + gh * 4) * 4), gsrc);
                cp_commit();
            }
            if (tid == 0) {
                bar_arrive(&g_bar[dir]);
                unsigned target = 64u * (unsigned)(t + 1);
                while (ld_acq(&g_bar[dir]) < target) { }
            }
            __syncthreads();
        }
    }
}

// ---------------- tag projection ---------------------------------------------
__global__ void __launch_bounds__(256) feats_kernel(const float* __restrict__ Wtag,
                                                    const float* __restrict__ btag) {
    int idx = blockIdx.x * 256 + threadIdx.x;   // 64*512*16
    int t = idx & 15;
    int l = (idx >> 4) & 511;
    int b = idx >> 13;
    const float4* hr = (const float4*)(g_hrow + (size_t)(l * 64 + b) * 1024);
    const float4* wr = (const float4*)(Wtag + (size_t)t * 1024);
    float a0 = 0.f, a1 = 0.f;
#pragma unroll 8
    for (int k = 0; k < 256; k += 2) {
        float4 x = hr[k],     w = wr[k];
        float4 y = hr[k + 1], v = wr[k + 1];
        a0 += x.x * w.x + x.y * w.y + x.z * w.z + x.w * w.w;
        a1 += y.x * v.x + y.y * v.y + y.z * v.z + y.w * v.w;
    }
    g_feats[((size_t)b * 512 + l) * 16 + t] = a0 + a1 + btag[t];
}

// ---------------- Viterbi -----------------------------------------------------
__global__ void __launch_bounds__(32) viterbi_kernel(const float* __restrict__ trans,
                                                     float* __restrict__ out) {
    int b = blockIdx.x;
    int lane = threadIdx.x;
    __shared__ unsigned char bp[512][16];
    __shared__ float smax[16];
    bool active = lane < 16;
    int row = active ? lane : 15;
    float tr[16];
#pragma unroll
    for (int j = 0; j < 16; j++) tr[j] = trans[row * 16 + j];
    float fv = (lane == 14) ? 0.0f : NEGV;   // START=14

    const float* fb = g_feats + (size_t)b * 512 * 16;
    for (int l = 0; l < 512; l++) {
        float best = -3.4e38f;
        int arg = 0;
#pragma unroll
        for (int j = 0; j < 16; j++) {
            float s = __shfl_sync(0xffffffffu, fv, j) + tr[j];
            if (s > best) { best = s; arg = j; }
        }
        float nf = best + fb[l * 16 + row];
        if (active) bp[l][lane] = (unsigned char)arg;
        fv = nf;
    }
    float term = fv + trans[15 * 16 + row];  // STOP=15
    if (active) smax[lane] = term;
    __syncwarp();
    if (lane == 0) {
        float best = smax[0]; int tag = 0;
        for (int j = 1; j < 16; j++) if (smax[j] > best) { best = smax[j]; tag = j; }
        out[b] = best;
        for (int l = 511; l >= 0; l--) {
            out[64 + b * 512 + l] = (float)tag;
            tag = bp[l][tag];
        }
    }
}

// ---------------- launch -------------------------------------------------------
extern "C" void kernel_launch(void* const* d_in, const int* in_sizes, int n_in,
                              void* d_out, int out_size) {
    const int*   sent  = (const int*)d_in[0];
    const float* embed = (const float*)d_in[1];
    const float* Wih_f = (const float*)d_in[2];
    const float* Whh_f = (const float*)d_in[3];
    const float* b_f   = (const float*)d_in[4];
    const float* Wih_b = (const float*)d_in[5];
    const float* Whh_b = (const float*)d_in[6];
    const float* b_b   = (const float*)d_in[7];
    const float* h0    = (const float*)d_in[8];
    const float* c0    = (const float*)d_in[9];
    const float* W_tag = (const float*)d_in[10];
    const float* b_tag = (const float*)d_in[11];
    const float* trans = (const float*)d_in[12];
    float* out = (float*)d_out;

    cudaFuncSetAttribute(lstm_persist, cudaFuncAttributeMaxDynamicSharedMemorySize, SMEM_BYTES);

    prepA<<<8448, 256>>>(Wih_f, Wih_b, h0);               // launch 1
    prepB<<<8192, 256>>>(Whh_f, Whh_b);                   // launch 2
    gemm1<<<dim3(32, 256), 256>>>(sent, embed, b_f, b_b);  // launch 3
    lstm_persist<<<128, 512, SMEM_BYTES>>>(c0);           // launch 4
    feats_kernel<<<2048, 256>>>(W_tag, b_tag);            // launch 5
    viterbi_kernel<<<64, 32>>>(trans, out);               // launch 6
}